// round 17
// baseline (speedup 1.0000x reference)
#include <cuda_runtime.h>
#include <cstdint>
#include <float.h>

#define FIN  128
#define FOUT 64
#define NEG  0.2f
#define NMAX 50048
#define EMAX 1000192

// ---------------- scratch (device globals; zero-initialized at load) --------
// Invariant: deg[], cursor[] are zero at entry; restored by gather epilogue.
__device__ float    g_Wh[NMAX * FOUT];
__device__ float    g_ssrc[NMAX];
__device__ float    g_sdst[NMAX];
__device__ int      g_deg[NMAX];
__device__ int      g_cursor[NMAX];
__device__ int      g_rowstart[NMAX];
__device__ uint2    g_bkt[EMAX];          // (src, bitcast(e)) bucketed by dst
__device__ int      g_total;              // bump allocator

// ---------------- per-block edge-dtype detect --------------------------------
__device__ __forceinline__ int detect_is64(const unsigned* eiw) {
    unsigned v = 0;
    if (threadIdx.x < 64) v = eiw[threadIdx.x * 2 + 1];
    return __syncthreads_or(v != 0u) ? 0 : 1;
}

__device__ __forceinline__ void load_edge(const void* ei, int is64, int E,
                                          int i, int N, int& s, int& d) {
    if (is64) {
        const long long* p = (const long long*)ei;
        s = (int)p[i];
        d = (int)p[E + i];
    } else {
        const int* p = (const int*)ei;
        s = p[i];
        d = p[E + i];
    }
    s = min(max(s, 0), N - 1);
    d = min(max(d, 0), N - 1);
}

// ---------------- 1) count: deg[dst]++ (dst stream only) --------------------
__global__ void count_kernel(const void* __restrict__ ei,
                             int* __restrict__ deg, int* __restrict__ total,
                             int E, int N) {
    int is64 = detect_is64((const unsigned*)ei);
    if (blockIdx.x == 0 && threadIdx.x == 0) *total = 0;
    for (int i = blockIdx.x * blockDim.x + threadIdx.x; i < E;
         i += gridDim.x * blockDim.x) {
        int d;
        if (is64) d = (int)((const long long*)ei)[E + i];
        else      d = ((const int*)ei)[E + i];
        d = min(max(d, 0), N - 1);
        atomicAdd(&deg[d], 1);
    }
}

// ---------------- 2) GEMM + s epilogue + alloc tail blocks ------------------
__global__ void gemm_kernel(const float* __restrict__ x,
                            const float* __restrict__ W,
                            const float* __restrict__ a_src,
                            const float* __restrict__ a_dst,
                            float* __restrict__ Wh,
                            float* __restrict__ ssrc,
                            float* __restrict__ sdst,
                            const int* __restrict__ deg,
                            int* __restrict__ rowstart,
                            int* __restrict__ total,
                            int gemmBlocks, int N) {
    extern __shared__ float sm[];
    int tid = threadIdx.x;

    // ======== alloc tail path (unordered bucket allocation) ========
    if (blockIdx.x >= gemmBlocks) {
        int* warpsum = (int*)sm;          // 8 ints
        int* blockbase = (int*)sm + 8;    // 1 int
        int i = (blockIdx.x - gemmBlocks) * blockDim.x + tid;
        int lane = tid & 31;
        int wid = tid >> 5;

        int v = (i < N) ? deg[i] : 0;
        int sc = v;
#pragma unroll
        for (int o = 1; o < 32; o <<= 1) {
            int t = __shfl_up_sync(0xFFFFFFFFu, sc, o);
            if (lane >= o) sc += t;
        }
        if (lane == 31) warpsum[wid] = sc;
        __syncthreads();
        if (tid < 8) {
            int ws = warpsum[tid];
            int s2 = ws;
#pragma unroll
            for (int o = 1; o < 8; o <<= 1) {
                int t = __shfl_up_sync(0xFFu, s2, o);
                if (tid >= o) s2 += t;
            }
            warpsum[tid] = s2 - ws;
            if (tid == 7) *blockbase = atomicAdd(total, s2);
        }
        __syncthreads();
        if (i < N) rowstart[i] = *blockbase + warpsum[wid] + (sc - v);
        return;
    }

    // ======== GEMM path ========
    float* xs = sm;              // 128*128
    float* ws = sm + 128 * 128;  // 128*64

    const float4* W4 = (const float4*)W;
    float4* ws4 = (float4*)ws;
#pragma unroll
    for (int i = 0; i < 8; i++) ws4[tid + i * 256] = W4[tid + i * 256];

    int r0 = blockIdx.x * 128;
    const float4* x4 = (const float4*)x;
    float4* xs4 = (float4*)xs;
#pragma unroll
    for (int i = 0; i < 16; i++) {
        int idx = tid + i * 256;
        int row = idx >> 5;
        int g = r0 + row;
        float4 v = make_float4(0.f, 0.f, 0.f, 0.f);
        if (g < N) v = x4[(size_t)g * 32 + (idx & 31)];
        xs4[idx] = v;
    }
    __syncthreads();

    int t16 = tid & 15;
    int colBase = t16 * 4;
    int rowBase = (tid >> 4) * 8;

    float acc[8][4];
#pragma unroll
    for (int i = 0; i < 8; i++)
#pragma unroll
        for (int j = 0; j < 4; j++) acc[i][j] = 0.f;

#pragma unroll 4
    for (int k4 = 0; k4 < 32; k4++) {
        float4 w0 = *(float4*)&ws[(k4 * 4 + 0) * 64 + colBase];
        float4 w1 = *(float4*)&ws[(k4 * 4 + 1) * 64 + colBase];
        float4 w2 = *(float4*)&ws[(k4 * 4 + 2) * 64 + colBase];
        float4 w3 = *(float4*)&ws[(k4 * 4 + 3) * 64 + colBase];
#pragma unroll
        for (int i = 0; i < 8; i++) {
            float4 xv = *(float4*)&xs[(rowBase + i) * 128 + k4 * 4];
            acc[i][0] += xv.x * w0.x + xv.y * w1.x + xv.z * w2.x + xv.w * w3.x;
            acc[i][1] += xv.x * w0.y + xv.y * w1.y + xv.z * w2.y + xv.w * w3.y;
            acc[i][2] += xv.x * w0.z + xv.y * w1.z + xv.z * w2.z + xv.w * w3.z;
            acc[i][3] += xv.x * w0.w + xv.y * w1.w + xv.z * w2.w + xv.w * w3.w;
        }
    }

    // fp32 store of Wh
#pragma unroll
    for (int i = 0; i < 8; i++) {
        int g = r0 + rowBase + i;
        if (g < N)
            *(float4*)&Wh[(size_t)g * FOUT + colBase] =
                make_float4(acc[i][0], acc[i][1], acc[i][2], acc[i][3]);
    }

    // fused s epilogue (fp32 accumulators)
    float4 asv = *(const float4*)&a_src[colBase];
    float4 adv = *(const float4*)&a_dst[colBase];

    __syncthreads();
    float* ps = sm;                // 128*17
    float* pd = sm + 128 * 17;     // 128*17
#pragma unroll
    for (int i = 0; i < 8; i++) {
        int row = rowBase + i;
        float vs = acc[i][0] * asv.x + acc[i][1] * asv.y +
                   acc[i][2] * asv.z + acc[i][3] * asv.w;
        float vd = acc[i][0] * adv.x + acc[i][1] * adv.y +
                   acc[i][2] * adv.z + acc[i][3] * adv.w;
        ps[row * 17 + t16] = vs;
        pd[row * 17 + t16] = vd;
    }
    __syncthreads();
    if (tid < 128) {
        float s1 = 0.f, s2 = 0.f;
#pragma unroll
        for (int k = 0; k < 16; k++) {
            s1 += ps[tid * 17 + k];
            s2 += pd[tid * 17 + k];
        }
        int g = r0 + tid;
        if (g < N) { ssrc[g] = s1; sdst[g] = s2; }
    }
}

// ---------------- 3) fill: e = exp(leaky(l)) unshifted; bucket by dst -------
__global__ void fill_kernel(const void* __restrict__ ei,
                            const float* __restrict__ ssrc,
                            const float* __restrict__ sdst,
                            const int* __restrict__ rowstart,
                            int* __restrict__ cursor,
                            uint2* __restrict__ bkt, int E, int N) {
    int is64 = detect_is64((const unsigned*)ei);
    int i = blockIdx.x * blockDim.x + threadIdx.x;
    if (i >= E) return;
    int s, d;
    load_edge(ei, is64, E, i, N, s, d);
    float t = ssrc[s] + sdst[d];
    float l = t > 0.f ? t : NEG * t;
    float e = __expf(l);
    int pos = atomicAdd(&cursor[d], 1);
    bkt[rowstart[d] + pos] = make_uint2((unsigned)s, __float_as_uint(e));
}

// ---------------- 4) gather: 16 thr/node, fp32, + state cleanup -------------
// 2 nodes/warp; lane owns 4 cols (one LDG.128 per edge). Per edge-thread:
// 1 bkt broadcast load + 1 float4 load + 4 FMA + 1 add — no conversions.
// 2-way unroll for MLP=4. Low regs -> high occupancy.
__global__ void gather_kernel(const uint2* __restrict__ bkt,
                              const int* __restrict__ rowstart,
                              int* __restrict__ deg,
                              int* __restrict__ cursor,
                              const float* __restrict__ Wh,
                              float* __restrict__ out, int N) {
    int t = blockIdx.x * blockDim.x + threadIdx.x;
    int node = t >> 4;
    int l = t & 15;
    if (node >= N) return;
    int beg = rowstart[node];
    int dg  = deg[node];
    int end = beg + dg;

    float4 a0 = make_float4(0.f, 0.f, 0.f, 0.f);
    float4 a1 = make_float4(0.f, 0.f, 0.f, 0.f);
    float den0 = 0.f, den1 = 0.f;

    int j = beg;
    for (; j + 2 <= end; j += 2) {
        uint2 b0 = __ldg(&bkt[j]);
        uint2 b1 = __ldg(&bkt[j + 1]);
        float4 w0 = __ldg((const float4*)&Wh[(size_t)b0.x * FOUT + l * 4]);
        float4 w1 = __ldg((const float4*)&Wh[(size_t)b1.x * FOUT + l * 4]);
        float e0 = __uint_as_float(b0.y);
        float e1 = __uint_as_float(b1.y);
        den0 += e0;
        den1 += e1;
        a0.x = fmaf(e0, w0.x, a0.x); a0.y = fmaf(e0, w0.y, a0.y);
        a0.z = fmaf(e0, w0.z, a0.z); a0.w = fmaf(e0, w0.w, a0.w);
        a1.x = fmaf(e1, w1.x, a1.x); a1.y = fmaf(e1, w1.y, a1.y);
        a1.z = fmaf(e1, w1.z, a1.z); a1.w = fmaf(e1, w1.w, a1.w);
    }
    if (j < end) {
        uint2 b0 = __ldg(&bkt[j]);
        float4 w0 = __ldg((const float4*)&Wh[(size_t)b0.x * FOUT + l * 4]);
        float e0 = __uint_as_float(b0.y);
        den0 += e0;
        a0.x = fmaf(e0, w0.x, a0.x); a0.y = fmaf(e0, w0.y, a0.y);
        a0.z = fmaf(e0, w0.z, a0.z); a0.w = fmaf(e0, w0.w, a0.w);
    }

    float inv = __fdividef(1.f, den0 + den1 + 1e-16f);
    float rx = (a0.x + a1.x) * inv;
    float ry = (a0.y + a1.y) * inv;
    float rz = (a0.z + a1.z) * inv;
    float rw = (a0.w + a1.w) * inv;
    rx = rx > 0.f ? rx : expm1f(rx);
    ry = ry > 0.f ? ry : expm1f(ry);
    rz = rz > 0.f ? rz : expm1f(rz);
    rw = rw > 0.f ? rw : expm1f(rw);
    *(float4*)&out[(size_t)node * FOUT + l * 4] = make_float4(rx, ry, rz, rw);

    // cleanup for next invocation
    if (l == 0) deg[node] = 0;
    if (l == 1) cursor[node] = 0;
}

// ---------------- launch ----------------------------------------------------
extern "C" void kernel_launch(void* const* d_in, const int* in_sizes, int n_in,
                              void* d_out, int out_size) {
    const float* x = 0;
    const void*  ei = 0;
    const float* W = 0;
    const float* a_src = 0;
    const float* a_dst = 0;
    int x_sz = 0, ei_sz = 0;

    for (int i = 0; i < n_in; i++) {
        int sz = in_sizes[i];
        if (sz == 64) {
            if (!a_src) a_src = (const float*)d_in[i];
            else        a_dst = (const float*)d_in[i];
        } else if (sz == FIN * FOUT) {
            W = (const float*)d_in[i];
        } else if (sz > x_sz) {
            ei = (const void*)x; ei_sz = x_sz;
            x = (const float*)d_in[i]; x_sz = sz;
        } else {
            ei = (const void*)d_in[i]; ei_sz = sz;
        }
    }

    float* out = (float*)d_out;
    int N = x_sz / FIN;
    int E = ei_sz / 2;

    void *pWh, *pss, *psd, *pdeg, *pcur, *prow, *pbkt, *ptot;
    cudaGetSymbolAddress(&pWh, g_Wh);
    cudaGetSymbolAddress(&pss, g_ssrc);
    cudaGetSymbolAddress(&psd, g_sdst);
    cudaGetSymbolAddress(&pdeg, g_deg);
    cudaGetSymbolAddress(&pcur, g_cursor);
    cudaGetSymbolAddress(&prow, g_rowstart);
    cudaGetSymbolAddress(&pbkt, g_bkt);
    cudaGetSymbolAddress(&ptot, g_total);

    count_kernel<<<1184, 256>>>(ei, (int*)pdeg, (int*)ptot, E, N);

    int gemmBlocks = (N + 127) / 128;
    int allocBlocks = (N + 255) / 256;
    cudaFuncSetAttribute(gemm_kernel,
                         cudaFuncAttributeMaxDynamicSharedMemorySize, 96 * 1024);
    gemm_kernel<<<gemmBlocks + allocBlocks, 256, 96 * 1024>>>(
        x, W, a_src, a_dst, (float*)pWh, (float*)pss, (float*)psd,
        (int*)pdeg, (int*)prow, (int*)ptot, gemmBlocks, N);

    fill_kernel<<<(E + 255) / 256, 256>>>(ei, (float*)pss, (float*)psd,
                                          (int*)prow, (int*)pcur,
                                          (uint2*)pbkt, E, N);

    long long gthreads = (long long)N * 16;
    gather_kernel<<<(int)((gthreads + 255) / 256), 256>>>(
        (uint2*)pbkt, (int*)prow, (int*)pdeg, (int*)pcur,
        (const float*)pWh, out, N);
}